// round 5
// baseline (speedup 1.0000x reference)
#include <cuda_runtime.h>
#include <cstdint>
#include <math.h>

#define N_NODES 50000
#define N_EDGES 800000
#define D_IN 8
#define D 128

// ---- scratch (static device globals; no allocation) ----
__device__ __align__(128) float g_bufX[N_NODES * D];   // h2
__device__ __align__(128) float g_bufH1[N_NODES * D];  // h1 -> A
__device__ __align__(128) float g_bufG[N_NODES * D];   // g  -> B
__device__ __align__(128) float g_xa[N_NODES * D_IN];  // aggregated x
__device__ float g_dinv[N_NODES];
__device__ int   g_cnt[N_NODES];
__device__ int   g_off[N_NODES + 1];
__device__ int   g_cur[N_NODES];
// AoS edge record in dst-sorted order: {src, dst, orig_eid, w(bits)}
__device__ __align__(16) int4 g_edge[N_EDGES];

// ---- packed f32x2 helpers ----
__device__ __forceinline__ unsigned long long pack2(float lo, float hi) {
    unsigned long long r;
    asm("mov.b64 %0, {%1, %2};" : "=l"(r) : "f"(lo), "f"(hi));
    return r;
}
__device__ __forceinline__ void fma2(unsigned long long& acc, unsigned long long a,
                                     unsigned long long b) {
    asm("fma.rn.f32x2 %0, %1, %2, %3;" : "=l"(acc) : "l"(a), "l"(b), "l"(acc));
}
__device__ __forceinline__ float2 unpack2(unsigned long long v) {
    float2 r;
    asm("mov.b64 {%0, %1}, %2;" : "=f"(r.x), "=f"(r.y) : "l"(v));
    return r;
}

// ---- CSR build ----
__global__ void k_count(const int* __restrict__ dst) {
    int t = blockIdx.x * blockDim.x + threadIdx.x;
    int e0 = t * 4;
    if (e0 + 4 <= N_EDGES) {
        int4 d4 = *(const int4*)&dst[e0];
        atomicAdd(&g_cnt[d4.x], 1);
        atomicAdd(&g_cnt[d4.y], 1);
        atomicAdd(&g_cnt[d4.z], 1);
        atomicAdd(&g_cnt[d4.w], 1);
    } else {
        for (int e = e0; e < N_EDGES; e++) atomicAdd(&g_cnt[dst[e]], 1);
    }
}

// thread-coarsened single-block scan: 1024 threads x ~49 elems each
__global__ void k_scan() {
    __shared__ int warp_sums[32];
    const int CH = (N_NODES + 1023) / 1024;  // 49
    int tid = threadIdx.x;
    int lane = tid & 31, wid = tid >> 5;
    int start = tid * CH;
    int end = min(start + CH, N_NODES);
    int sum = 0;
    for (int i = start; i < end; i++) sum += g_cnt[i];
    int v = sum;
#pragma unroll
    for (int o = 1; o < 32; o <<= 1) {
        int t = __shfl_up_sync(0xffffffffu, v, o);
        if (lane >= o) v += t;
    }
    if (lane == 31) warp_sums[wid] = v;
    __syncthreads();
    if (wid == 0) {
        int s = warp_sums[lane];
#pragma unroll
        for (int o = 1; o < 32; o <<= 1) {
            int t = __shfl_up_sync(0xffffffffu, s, o);
            if (lane >= o) s += t;
        }
        warp_sums[lane] = s;
    }
    __syncthreads();
    int run = v - sum + (wid > 0 ? warp_sums[wid - 1] : 0);  // exclusive prefix
    for (int i = start; i < end; i++) {
        int c = g_cnt[i];
        g_cur[i] = run;
        run += c;
        g_off[i + 1] = run;
        g_dinv[i] = rsqrtf((float)c + 1.0f);  // deg = cnt + 1 (self-loop)
    }
    if (tid == 0) g_off[0] = 0;
}

__global__ void k_fill(const int* __restrict__ src, const int* __restrict__ dst) {
    int t = blockIdx.x * blockDim.x + threadIdx.x;
    int e0 = t * 4;
    if (e0 >= N_EDGES) return;
    int4 s4 = *(const int4*)&src[e0];
    int4 d4 = *(const int4*)&dst[e0];
#pragma unroll
    for (int j = 0; j < 4; j++) {
        int s = (j == 0) ? s4.x : (j == 1) ? s4.y : (j == 2) ? s4.z : s4.w;
        int d = (j == 0) ? d4.x : (j == 1) ? d4.y : (j == 2) ? d4.z : d4.w;
        int p = atomicAdd(&g_cur[d], 1);
        float w = g_dinv[s] * g_dinv[d];
        g_edge[p] = make_int4(s, d, e0 + j, __float_as_int(w));
    }
}

// ---- layer-1: aggregate raw x over 8 dims (agg is linear; W1 applied after) ----
// thread = (node, dim): warp covers 4 nodes x 8 dims
__global__ void k_agg_in(const float* __restrict__ x) {
    int gid = blockIdx.x * blockDim.x + threadIdx.x;
    int n = gid >> 3;
    int dim = gid & 7;
    if (n >= N_NODES) return;
    float di = g_dinv[n];
    float acc = x[n * D_IN + dim] * di * di;
    int i0 = g_off[n], i1 = g_off[n + 1];
    for (int i = i0; i < i1; i++) {
        int4 ed = g_edge[i];
        acc = fmaf(x[ed.x * D_IN + dim], __int_as_float(ed.w), acc);
    }
    g_xa[n * D_IN + dim] = acc;
}

// ---- h1 = relu(xa @ W1 + b1), xa[50000,8], W1[8,128] ----
__global__ void k_gemm_in(const float* __restrict__ xa, const float* __restrict__ W1,
                          const float* __restrict__ b1, float* __restrict__ H) {
    int node = blockIdx.x * 2 + (threadIdx.x >> 7);
    int j = threadIdx.x & 127;
    if (node >= N_NODES) return;
    float s = b1[j];
#pragma unroll
    for (int k = 0; k < D_IN; k++)
        s = fmaf(xa[node * D_IN + k], W1[k * D + j], s);
    H[node * D + j] = fmaxf(s, 0.f);
}

// ---- 128-dim aggregation + bias + relu: warp per node, float4 lanes ----
__global__ void k_aggregate(const float* __restrict__ Hin, const float* __restrict__ bias,
                            float* __restrict__ Hout) {
    int n = (blockIdx.x * blockDim.x + threadIdx.x) >> 5;
    int lane = threadIdx.x & 31;
    if (n >= N_NODES) return;
    float di = g_dinv[n];
    float wself = di * di;
    float4 self = *(const float4*)&Hin[n * D + lane * 4];
    float4 acc = make_float4(self.x * wself, self.y * wself, self.z * wself, self.w * wself);
    int i0 = g_off[n], i1 = g_off[n + 1];
    int i = i0;
    for (; i + 2 <= i1; i += 2) {
        int4 e0 = g_edge[i], e1 = g_edge[i + 1];
        float w0 = __int_as_float(e0.w), w1 = __int_as_float(e1.w);
        float4 v0 = *(const float4*)&Hin[e0.x * D + lane * 4];
        float4 v1 = *(const float4*)&Hin[e1.x * D + lane * 4];
        acc.x = fmaf(v0.x, w0, acc.x); acc.y = fmaf(v0.y, w0, acc.y);
        acc.z = fmaf(v0.z, w0, acc.z); acc.w = fmaf(v0.w, w0, acc.w);
        acc.x = fmaf(v1.x, w1, acc.x); acc.y = fmaf(v1.y, w1, acc.y);
        acc.z = fmaf(v1.z, w1, acc.z); acc.w = fmaf(v1.w, w1, acc.w);
    }
    if (i < i1) {
        int4 e0 = g_edge[i];
        float w0 = __int_as_float(e0.w);
        float4 v0 = *(const float4*)&Hin[e0.x * D + lane * 4];
        acc.x = fmaf(v0.x, w0, acc.x); acc.y = fmaf(v0.y, w0, acc.y);
        acc.z = fmaf(v0.z, w0, acc.z); acc.w = fmaf(v0.w, w0, acc.w);
    }
    float4 bv = *(const float4*)&bias[lane * 4];
    float4 o = make_float4(fmaxf(acc.x + bv.x, 0.f), fmaxf(acc.y + bv.y, 0.f),
                           fmaxf(acc.z + bv.z, 0.f), fmaxf(acc.w + bv.w, 0.f));
    *(float4*)&Hout[n * D + lane * 4] = o;
}

// ---- dense C[M,128] = H[M,128] @ W[128,128], packed f32x2 FMA ----
__global__ void __launch_bounds__(256) k_gemm128(
    const float* __restrict__ H, const float* __restrict__ W,
    float* __restrict__ C) {
    extern __shared__ float smem[];
    float* Ws = smem;          // 128*128
    float* Hs = smem + D * D;  // 64*128
    int tid = threadIdx.x;
    for (int i = tid * 4; i < D * D; i += 256 * 4)
        *(float4*)&Ws[i] = *(const float4*)&W[i];
    int row0 = blockIdx.x * 64;
    for (int i = tid * 4; i < 64 * D; i += 256 * 4) {
        int r = row0 + (i >> 7);
        float4 v = make_float4(0.f, 0.f, 0.f, 0.f);
        if (r < N_NODES) v = *(const float4*)&H[r * D + (i & 127)];
        *(float4*)&Hs[i] = v;
    }
    __syncthreads();
    int warp = tid >> 5, lane = tid & 31;
    unsigned long long acc01[8], acc23[8];
#pragma unroll
    for (int n = 0; n < 8; n++) { acc01[n] = 0ull; acc23[n] = 0ull; }
    const float* hrow = &Hs[warp * 8 * D];
    for (int k0 = 0; k0 < D; k0 += 4) {
        float4 hreg[8];
#pragma unroll
        for (int n = 0; n < 8; n++)
            hreg[n] = *(const float4*)&hrow[n * D + k0];
#pragma unroll
        for (int kk = 0; kk < 4; kk++) {
            float4 w = *(const float4*)&Ws[(k0 + kk) * D + lane * 4];
            unsigned long long w01 = pack2(w.x, w.y);
            unsigned long long w23 = pack2(w.z, w.w);
#pragma unroll
            for (int n = 0; n < 8; n++) {
                float h = (kk == 0) ? hreg[n].x : (kk == 1) ? hreg[n].y
                         : (kk == 2) ? hreg[n].z : hreg[n].w;
                unsigned long long h2 = pack2(h, h);
                fma2(acc01[n], h2, w01);
                fma2(acc23[n], h2, w23);
            }
        }
    }
#pragma unroll
    for (int n = 0; n < 8; n++) {
        int r = row0 + warp * 8 + n;
        if (r < N_NODES) {
            float2 p01 = unpack2(acc01[n]);
            float2 p23 = unpack2(acc23[n]);
            float4 o = make_float4(p01.x, p01.y, p23.x, p23.y);
            *(float4*)&C[r * D + lane * 4] = o;
        }
    }
}

// ---- fused A/B: A = H@Wtop + blin1, B = H@Wbot (Wlin1 [256,128]) ----
__global__ void __launch_bounds__(256) k_gemmAB(
    const float* __restrict__ H, const float* __restrict__ Wlin1,
    const float* __restrict__ blin1, float* __restrict__ A, float* __restrict__ B) {
    extern __shared__ float smem[];
    float* Wa = smem;               // 128*128
    float* Wb = smem + D * D;       // 128*128
    float* Hs = smem + 2 * D * D;   // 64*128
    int tid = threadIdx.x;
    for (int i = tid * 4; i < D * D; i += 256 * 4) {
        *(float4*)&Wa[i] = *(const float4*)&Wlin1[i];
        *(float4*)&Wb[i] = *(const float4*)&Wlin1[D * D + i];
    }
    int row0 = blockIdx.x * 64;
    for (int i = tid * 4; i < 64 * D; i += 256 * 4) {
        int r = row0 + (i >> 7);
        float4 v = make_float4(0.f, 0.f, 0.f, 0.f);
        if (r < N_NODES) v = *(const float4*)&H[r * D + (i & 127)];
        *(float4*)&Hs[i] = v;
    }
    __syncthreads();
    int warp = tid >> 5, lane = tid & 31;
    unsigned long long accA01[8], accA23[8], accB01[8], accB23[8];
#pragma unroll
    for (int n = 0; n < 8; n++) {
        accA01[n] = accA23[n] = accB01[n] = accB23[n] = 0ull;
    }
    const float* hrow = &Hs[warp * 8 * D];
    for (int k0 = 0; k0 < D; k0 += 4) {
        float4 hreg[8];
#pragma unroll
        for (int n = 0; n < 8; n++)
            hreg[n] = *(const float4*)&hrow[n * D + k0];
#pragma unroll
        for (int kk = 0; kk < 4; kk++) {
            float4 wa = *(const float4*)&Wa[(k0 + kk) * D + lane * 4];
            float4 wb = *(const float4*)&Wb[(k0 + kk) * D + lane * 4];
            unsigned long long wa01 = pack2(wa.x, wa.y);
            unsigned long long wa23 = pack2(wa.z, wa.w);
            unsigned long long wb01 = pack2(wb.x, wb.y);
            unsigned long long wb23 = pack2(wb.z, wb.w);
#pragma unroll
            for (int n = 0; n < 8; n++) {
                float h = (kk == 0) ? hreg[n].x : (kk == 1) ? hreg[n].y
                         : (kk == 2) ? hreg[n].z : hreg[n].w;
                unsigned long long h2 = pack2(h, h);
                fma2(accA01[n], h2, wa01);
                fma2(accA23[n], h2, wa23);
                fma2(accB01[n], h2, wb01);
                fma2(accB23[n], h2, wb23);
            }
        }
    }
    float4 bv = *(const float4*)&blin1[lane * 4];
#pragma unroll
    for (int n = 0; n < 8; n++) {
        int r = row0 + warp * 8 + n;
        if (r < N_NODES) {
            float2 a01 = unpack2(accA01[n]);
            float2 a23 = unpack2(accA23[n]);
            float2 b01 = unpack2(accB01[n]);
            float2 b23 = unpack2(accB23[n]);
            *(float4*)&A[r * D + lane * 4] =
                make_float4(a01.x + bv.x, a01.y + bv.y, a23.x + bv.z, a23.y + bv.w);
            *(float4*)&B[r * D + lane * 4] = make_float4(b01.x, b01.y, b23.x, b23.y);
        }
    }
}

// ---- per-edge head over dst-sorted records (B rows reused via L1) ----
__global__ void k_edge_out(const float* __restrict__ A, const float* __restrict__ B,
                           const float* __restrict__ Wfin, const float* __restrict__ bfin,
                           float* __restrict__ out) {
    int gid = blockIdx.x * blockDim.x + threadIdx.x;
    int p = gid >> 5;
    int lane = gid & 31;
    if (p >= N_EDGES) return;
    int4 ed = g_edge[p];   // {src, dst, eid, w}
    float4 a = *(const float4*)&A[ed.x * D + lane * 4];
    float4 b = *(const float4*)&B[ed.y * D + lane * 4];
    float v0 = fmaxf(a.x + b.x, 0.f);
    float v1 = fmaxf(a.y + b.y, 0.f);
    float v2 = fmaxf(a.z + b.z, 0.f);
    float v3 = fmaxf(a.w + b.w, 0.f);
    float4 w01 = *(const float4*)&Wfin[lane * 8];
    float4 w23 = *(const float4*)&Wfin[lane * 8 + 4];
    float l0 = v0 * w01.x + v1 * w01.z + v2 * w23.x + v3 * w23.z;
    float l1 = v0 * w01.y + v1 * w01.w + v2 * w23.y + v3 * w23.w;
#pragma unroll
    for (int o = 16; o; o >>= 1) {
        l0 += __shfl_xor_sync(0xffffffffu, l0, o);
        l1 += __shfl_xor_sync(0xffffffffu, l1, o);
    }
    if (lane == 0) {
        l0 += bfin[0];
        l1 += bfin[1];
        float m = fmaxf(l0, l1);
        float lse = m + __logf(__expf(l0 - m) + __expf(l1 - m));
        *(float2*)&out[2 * ed.z] = make_float2(l0 - lse, l1 - lse);
    }
}

extern "C" void kernel_launch(void* const* d_in, const int* in_sizes, int n_in,
                              void* d_out, int out_size) {
    const float* x     = (const float*)d_in[0];
    const int*   ei    = (const int*)d_in[1];
    const float* W1    = (const float*)d_in[2];
    const float* b1    = (const float*)d_in[3];
    const float* W2    = (const float*)d_in[4];
    const float* b2    = (const float*)d_in[5];
    const float* Wlin1 = (const float*)d_in[6];
    const float* blin1 = (const float*)d_in[7];
    const float* Wfin  = (const float*)d_in[8];
    const float* bfin  = (const float*)d_in[9];
    const int* src = ei;
    const int* dst = ei + N_EDGES;
    float* out = (float*)d_out;

    void *pX, *pH1, *pG, *pXA, *pCnt;
    cudaGetSymbolAddress(&pX, g_bufX);
    cudaGetSymbolAddress(&pH1, g_bufH1);
    cudaGetSymbolAddress(&pG, g_bufG);
    cudaGetSymbolAddress(&pXA, g_xa);
    cudaGetSymbolAddress(&pCnt, g_cnt);
    float* bufX  = (float*)pX;
    float* bufH1 = (float*)pH1;
    float* bufG  = (float*)pG;
    float* xa    = (float*)pXA;

    const int gemm_smem = (D * D + 64 * D) * 4;          // 96 KB
    const int gemmAB_smem = (2 * D * D + 64 * D) * 4;    // 160 KB
    cudaFuncSetAttribute(k_gemm128, cudaFuncAttributeMaxDynamicSharedMemorySize, gemm_smem);
    cudaFuncSetAttribute(k_gemmAB, cudaFuncAttributeMaxDynamicSharedMemorySize, gemmAB_smem);

    // graph structure (rebuilt every call)
    cudaMemsetAsync(pCnt, 0, N_NODES * sizeof(int));
    k_count<<<(N_EDGES / 4 + 255) / 256, 256>>>(dst);
    k_scan<<<1, 1024>>>();
    k_fill<<<(N_EDGES / 4 + 255) / 256, 256>>>(src, dst);

    // layer 1: aggregate x (8 dims) then project
    k_agg_in<<<(N_NODES * 8 + 255) / 256, 256>>>(x);                      // xa
    k_gemm_in<<<N_NODES / 2, 256>>>(xa, W1, b1, bufH1);                   // h1

    // layer 2
    k_gemm128<<<(N_NODES + 63) / 64, 256, gemm_smem>>>(bufH1, W2, bufG);  // g
    k_aggregate<<<(N_NODES * 32 + 255) / 256, 256>>>(bufG, b2, bufX);     // h2

    // per-node halves of the edge MLP (concat trick), fused
    k_gemmAB<<<(N_NODES + 63) / 64, 256, gemmAB_smem>>>(bufX, Wlin1, blin1, bufH1, bufG);

    // per-edge head over dst-sorted order
    k_edge_out<<<(N_EDGES * 32 + 255) / 256, 256>>>(bufH1, bufG, Wfin, bfin, out);
}

// round 7
// speedup vs baseline: 1.0339x; 1.0339x over previous
#include <cuda_runtime.h>
#include <cstdint>
#include <math.h>

#define N_NODES 50000
#define N_EDGES 800000
#define D_IN 8
#define D 128

// ---- scratch (static device globals; no allocation) ----
__device__ __align__(128) float g_bufX[N_NODES * D];   // h2
__device__ __align__(128) float g_bufH1[N_NODES * D];  // h1 -> A
__device__ __align__(128) float g_bufG[N_NODES * D];   // g  -> B
__device__ float g_dinv[N_NODES];
__device__ int   g_cnt[N_NODES];
__device__ int   g_off[N_NODES + 1];
__device__ int   g_cur[N_NODES];
// AoS edge record in dst-sorted order: {src, dst, orig_eid, w(bits)}
__device__ __align__(16) int4 g_edge[N_EDGES];

// ---- packed f32x2 helpers ----
__device__ __forceinline__ unsigned long long pack2(float lo, float hi) {
    unsigned long long r;
    asm("mov.b64 %0, {%1, %2};" : "=l"(r) : "f"(lo), "f"(hi));
    return r;
}
__device__ __forceinline__ void fma2(unsigned long long& acc, unsigned long long a,
                                     unsigned long long b) {
    asm("fma.rn.f32x2 %0, %1, %2, %3;" : "=l"(acc) : "l"(a), "l"(b), "l"(acc));
}
__device__ __forceinline__ float2 unpack2(unsigned long long v) {
    float2 r;
    asm("mov.b64 {%0, %1}, %2;" : "=f"(r.x), "=f"(r.y) : "l"(v));
    return r;
}

// ---- CSR build ----
__global__ void k_count(const int* __restrict__ dst) {
    int t = blockIdx.x * blockDim.x + threadIdx.x;
    int e0 = t * 4;
    if (e0 + 4 <= N_EDGES) {
        int4 d4 = *(const int4*)&dst[e0];
        atomicAdd(&g_cnt[d4.x], 1);
        atomicAdd(&g_cnt[d4.y], 1);
        atomicAdd(&g_cnt[d4.z], 1);
        atomicAdd(&g_cnt[d4.w], 1);
    } else {
        for (int e = e0; e < N_EDGES; e++) atomicAdd(&g_cnt[dst[e]], 1);
    }
}

// thread-coarsened single-block scan: 1024 threads x ~49 elems each
__global__ void k_scan() {
    __shared__ int warp_sums[32];
    const int CH = (N_NODES + 1023) / 1024;  // 49
    int tid = threadIdx.x;
    int lane = tid & 31, wid = tid >> 5;
    int start = tid * CH;
    int end = min(start + CH, N_NODES);
    int sum = 0;
    for (int i = start; i < end; i++) sum += g_cnt[i];
    int v = sum;
#pragma unroll
    for (int o = 1; o < 32; o <<= 1) {
        int t = __shfl_up_sync(0xffffffffu, v, o);
        if (lane >= o) v += t;
    }
    if (lane == 31) warp_sums[wid] = v;
    __syncthreads();
    if (wid == 0) {
        int s = warp_sums[lane];
#pragma unroll
        for (int o = 1; o < 32; o <<= 1) {
            int t = __shfl_up_sync(0xffffffffu, s, o);
            if (lane >= o) s += t;
        }
        warp_sums[lane] = s;
    }
    __syncthreads();
    int run = v - sum + (wid > 0 ? warp_sums[wid - 1] : 0);  // exclusive prefix
    for (int i = start; i < end; i++) {
        int c = g_cnt[i];
        g_cur[i] = run;
        run += c;
        g_off[i + 1] = run;
        g_dinv[i] = rsqrtf((float)c + 1.0f);  // deg = cnt + 1 (self-loop)
    }
    if (tid == 0) g_off[0] = 0;
}

__global__ void k_fill(const int* __restrict__ src, const int* __restrict__ dst) {
    int t = blockIdx.x * blockDim.x + threadIdx.x;
    int e0 = t * 4;
    if (e0 >= N_EDGES) return;
    int4 s4 = *(const int4*)&src[e0];
    int4 d4 = *(const int4*)&dst[e0];
#pragma unroll
    for (int j = 0; j < 4; j++) {
        int s = (j == 0) ? s4.x : (j == 1) ? s4.y : (j == 2) ? s4.z : s4.w;
        int d = (j == 0) ? d4.x : (j == 1) ? d4.y : (j == 2) ? d4.z : d4.w;
        int p = atomicAdd(&g_cur[d], 1);
        float w = g_dinv[s] * g_dinv[d];
        g_edge[p] = make_int4(s, d, e0 + j, __float_as_int(w));
    }
}

// ---- fused layer-1: h1 = relu( agg(x) @ W1 + b1 ), warp per node ----
// agg over D_IN=8 dims: 4 lane-groups of 8 (dim = lane&7), 4 edges in flight;
// shfl-reduce groups, shfl-broadcast dims, project to 128 with W1 in smem.
__global__ void __launch_bounds__(256) k_layer1(
    const float* __restrict__ x, const float* __restrict__ W1,
    const float* __restrict__ b1, float* __restrict__ H) {
    __shared__ float sW1[D_IN * D];
    for (int i = threadIdx.x * 4; i < D_IN * D; i += 256 * 4)
        *(float4*)&sW1[i] = *(const float4*)&W1[i];
    __syncthreads();
    int n = (blockIdx.x * blockDim.x + threadIdx.x) >> 5;
    if (n >= N_NODES) return;
    int lane = threadIdx.x & 31;
    int grp = lane >> 3;    // 0..3
    int dim = lane & 7;     // 0..7
    float di = g_dinv[n];
    float acc = (grp == 0) ? x[n * D_IN + dim] * di * di : 0.f;
    int i0 = g_off[n], i1 = g_off[n + 1];
    for (int i = i0 + grp; i < i1; i += 4) {
        int4 ed = g_edge[i];
        acc = fmaf(x[ed.x * D_IN + dim], __int_as_float(ed.w), acc);
    }
    // reduce across the 4 groups
    acc += __shfl_xor_sync(0xffffffffu, acc, 8);
    acc += __shfl_xor_sync(0xffffffffu, acc, 16);
    // broadcast all 8 aggregated dims to every lane
    float xav[D_IN];
#pragma unroll
    for (int k = 0; k < D_IN; k++)
        xav[k] = __shfl_sync(0xffffffffu, acc, k);
    // project: 4 output cols per lane
    float4 o = *(const float4*)&b1[lane * 4];
#pragma unroll
    for (int k = 0; k < D_IN; k++) {
        float4 w = *(const float4*)&sW1[k * D + lane * 4];
        o.x = fmaf(xav[k], w.x, o.x);
        o.y = fmaf(xav[k], w.y, o.y);
        o.z = fmaf(xav[k], w.z, o.z);
        o.w = fmaf(xav[k], w.w, o.w);
    }
    o = make_float4(fmaxf(o.x, 0.f), fmaxf(o.y, 0.f), fmaxf(o.z, 0.f), fmaxf(o.w, 0.f));
    *(float4*)&H[n * D + lane * 4] = o;
}

// ---- 128-dim aggregation + bias + relu: warp per node, float4 lanes, 4-wide MLP ----
__global__ void k_aggregate(const float* __restrict__ Hin, const float* __restrict__ bias,
                            float* __restrict__ Hout) {
    int n = (blockIdx.x * blockDim.x + threadIdx.x) >> 5;
    int lane = threadIdx.x & 31;
    if (n >= N_NODES) return;
    float di = g_dinv[n];
    float wself = di * di;
    float4 self = *(const float4*)&Hin[n * D + lane * 4];
    float4 acc = make_float4(self.x * wself, self.y * wself, self.z * wself, self.w * wself);
    int i0 = g_off[n], i1 = g_off[n + 1];
    int i = i0;
    for (; i + 4 <= i1; i += 4) {
        int4 e0 = g_edge[i], e1 = g_edge[i + 1], e2 = g_edge[i + 2], e3 = g_edge[i + 3];
        float w0 = __int_as_float(e0.w), w1 = __int_as_float(e1.w);
        float w2 = __int_as_float(e2.w), w3 = __int_as_float(e3.w);
        float4 v0 = *(const float4*)&Hin[e0.x * D + lane * 4];
        float4 v1 = *(const float4*)&Hin[e1.x * D + lane * 4];
        float4 v2 = *(const float4*)&Hin[e2.x * D + lane * 4];
        float4 v3 = *(const float4*)&Hin[e3.x * D + lane * 4];
        acc.x = fmaf(v0.x, w0, acc.x); acc.y = fmaf(v0.y, w0, acc.y);
        acc.z = fmaf(v0.z, w0, acc.z); acc.w = fmaf(v0.w, w0, acc.w);
        acc.x = fmaf(v1.x, w1, acc.x); acc.y = fmaf(v1.y, w1, acc.y);
        acc.z = fmaf(v1.z, w1, acc.z); acc.w = fmaf(v1.w, w1, acc.w);
        acc.x = fmaf(v2.x, w2, acc.x); acc.y = fmaf(v2.y, w2, acc.y);
        acc.z = fmaf(v2.z, w2, acc.z); acc.w = fmaf(v2.w, w2, acc.w);
        acc.x = fmaf(v3.x, w3, acc.x); acc.y = fmaf(v3.y, w3, acc.y);
        acc.z = fmaf(v3.z, w3, acc.z); acc.w = fmaf(v3.w, w3, acc.w);
    }
    for (; i < i1; i++) {
        int4 e0 = g_edge[i];
        float w0 = __int_as_float(e0.w);
        float4 v0 = *(const float4*)&Hin[e0.x * D + lane * 4];
        acc.x = fmaf(v0.x, w0, acc.x); acc.y = fmaf(v0.y, w0, acc.y);
        acc.z = fmaf(v0.z, w0, acc.z); acc.w = fmaf(v0.w, w0, acc.w);
    }
    float4 bv = *(const float4*)&bias[lane * 4];
    float4 o = make_float4(fmaxf(acc.x + bv.x, 0.f), fmaxf(acc.y + bv.y, 0.f),
                           fmaxf(acc.z + bv.z, 0.f), fmaxf(acc.w + bv.w, 0.f));
    *(float4*)&Hout[n * D + lane * 4] = o;
}

// ---- dense C[M,128] = H[M,128] @ W[128,128] (+opt bias), packed f32x2 FMA ----
// 256 threads, 64 rows/block; W in smem; 2 CTAs/SM at 96KB.
__global__ void __launch_bounds__(256) k_gemm128(
    const float* __restrict__ H, const float* __restrict__ W,
    const float* __restrict__ bias, float* __restrict__ C) {
    extern __shared__ float smem[];
    float* Ws = smem;          // 128*128
    float* Hs = smem + D * D;  // 64*128
    int tid = threadIdx.x;
    for (int i = tid * 4; i < D * D; i += 256 * 4)
        *(float4*)&Ws[i] = *(const float4*)&W[i];
    int row0 = blockIdx.x * 64;
    for (int i = tid * 4; i < 64 * D; i += 256 * 4) {
        int r = row0 + (i >> 7);
        float4 v = make_float4(0.f, 0.f, 0.f, 0.f);
        if (r < N_NODES) v = *(const float4*)&H[r * D + (i & 127)];
        *(float4*)&Hs[i] = v;
    }
    __syncthreads();
    int warp = tid >> 5, lane = tid & 31;
    unsigned long long acc01[8], acc23[8];
#pragma unroll
    for (int n = 0; n < 8; n++) { acc01[n] = 0ull; acc23[n] = 0ull; }
    const float* hrow = &Hs[warp * 8 * D];
    for (int k0 = 0; k0 < D; k0 += 4) {
        float4 hreg[8];
#pragma unroll
        for (int n = 0; n < 8; n++)
            hreg[n] = *(const float4*)&hrow[n * D + k0];
#pragma unroll
        for (int kk = 0; kk < 4; kk++) {
            float4 w = *(const float4*)&Ws[(k0 + kk) * D + lane * 4];
            unsigned long long w01 = pack2(w.x, w.y);
            unsigned long long w23 = pack2(w.z, w.w);
#pragma unroll
            for (int n = 0; n < 8; n++) {
                float h = (kk == 0) ? hreg[n].x : (kk == 1) ? hreg[n].y
                         : (kk == 2) ? hreg[n].z : hreg[n].w;
                unsigned long long h2 = pack2(h, h);
                fma2(acc01[n], h2, w01);
                fma2(acc23[n], h2, w23);
            }
        }
    }
    float4 bv = make_float4(0.f, 0.f, 0.f, 0.f);
    if (bias) bv = *(const float4*)&bias[lane * 4];
#pragma unroll
    for (int n = 0; n < 8; n++) {
        int r = row0 + warp * 8 + n;
        if (r < N_NODES) {
            float2 p01 = unpack2(acc01[n]);
            float2 p23 = unpack2(acc23[n]);
            float4 o = make_float4(p01.x + bv.x, p01.y + bv.y, p23.x + bv.z, p23.y + bv.w);
            *(float4*)&C[r * D + lane * 4] = o;
        }
    }
}

// ---- per-edge head over dst-sorted records (B rows reused via L1) ----
__global__ void k_edge_out(const float* __restrict__ A, const float* __restrict__ B,
                           const float* __restrict__ Wfin, const float* __restrict__ bfin,
                           float* __restrict__ out) {
    int gid = blockIdx.x * blockDim.x + threadIdx.x;
    int p = gid >> 5;
    int lane = gid & 31;
    if (p >= N_EDGES) return;
    int4 ed = g_edge[p];   // {src, dst, eid, w}
    float4 a = *(const float4*)&A[ed.x * D + lane * 4];
    float4 b = *(const float4*)&B[ed.y * D + lane * 4];
    float v0 = fmaxf(a.x + b.x, 0.f);
    float v1 = fmaxf(a.y + b.y, 0.f);
    float v2 = fmaxf(a.z + b.z, 0.f);
    float v3 = fmaxf(a.w + b.w, 0.f);
    float4 w01 = *(const float4*)&Wfin[lane * 8];
    float4 w23 = *(const float4*)&Wfin[lane * 8 + 4];
    float l0 = v0 * w01.x + v1 * w01.z + v2 * w23.x + v3 * w23.z;
    float l1 = v0 * w01.y + v1 * w01.w + v2 * w23.y + v3 * w23.w;
#pragma unroll
    for (int o = 16; o; o >>= 1) {
        l0 += __shfl_xor_sync(0xffffffffu, l0, o);
        l1 += __shfl_xor_sync(0xffffffffu, l1, o);
    }
    if (lane == 0) {
        l0 += bfin[0];
        l1 += bfin[1];
        float m = fmaxf(l0, l1);
        float lse = m + __logf(__expf(l0 - m) + __expf(l1 - m));
        *(float2*)&out[2 * ed.z] = make_float2(l0 - lse, l1 - lse);
    }
}

extern "C" void kernel_launch(void* const* d_in, const int* in_sizes, int n_in,
                              void* d_out, int out_size) {
    const float* x     = (const float*)d_in[0];
    const int*   ei    = (const int*)d_in[1];
    const float* W1    = (const float*)d_in[2];
    const float* b1    = (const float*)d_in[3];
    const float* W2    = (const float*)d_in[4];
    const float* b2    = (const float*)d_in[5];
    const float* Wlin1 = (const float*)d_in[6];
    const float* blin1 = (const float*)d_in[7];
    const float* Wfin  = (const float*)d_in[8];
    const float* bfin  = (const float*)d_in[9];
    const int* src = ei;
    const int* dst = ei + N_EDGES;
    float* out = (float*)d_out;

    void *pX, *pH1, *pG, *pCnt;
    cudaGetSymbolAddress(&pX, g_bufX);
    cudaGetSymbolAddress(&pH1, g_bufH1);
    cudaGetSymbolAddress(&pG, g_bufG);
    cudaGetSymbolAddress(&pCnt, g_cnt);
    float* bufX  = (float*)pX;
    float* bufH1 = (float*)pH1;
    float* bufG  = (float*)pG;

    const int gemm_smem = (D * D + 64 * D) * 4;  // 96 KB -> 2 CTAs/SM
    cudaFuncSetAttribute(k_gemm128, cudaFuncAttributeMaxDynamicSharedMemorySize, gemm_smem);

    // graph structure (rebuilt every call)
    cudaMemsetAsync(pCnt, 0, N_NODES * sizeof(int));
    k_count<<<(N_EDGES / 4 + 255) / 256, 256>>>(dst);
    k_scan<<<1, 1024>>>();
    k_fill<<<(N_EDGES / 4 + 255) / 256, 256>>>(src, dst);

    // layer 1: fused aggregate(x) + projection + bias + relu
    k_layer1<<<(N_NODES * 32 + 255) / 256, 256>>>(x, W1, b1, bufH1);      // h1

    // layer 2
    k_gemm128<<<(N_NODES + 63) / 64, 256, gemm_smem>>>(bufH1, W2, nullptr, bufG);  // g
    k_aggregate<<<(N_NODES * 32 + 255) / 256, 256>>>(bufG, b2, bufX);     // h2

    // per-node halves of the edge MLP (concat trick)
    k_gemm128<<<(N_NODES + 63) / 64, 256, gemm_smem>>>(bufX, Wlin1, blin1, bufH1);          // A
    k_gemm128<<<(N_NODES + 63) / 64, 256, gemm_smem>>>(bufX, Wlin1 + D * D, nullptr, bufG); // B

    // per-edge head over dst-sorted order
    k_edge_out<<<(N_EDGES * 32 + 255) / 256, 256>>>(bufH1, bufG, Wfin, bfin, out);
}

// round 10
// speedup vs baseline: 1.0445x; 1.0103x over previous
#include <cuda_runtime.h>
#include <cstdint>
#include <math.h>

#define N_NODES 50000
#define N_EDGES 800000
#define D_IN 8
#define D 128
#define GEMM_TILES ((N_NODES + 63) / 64)   // 782
#define GEMM_GRID 296

typedef unsigned long long ull;

// ---- scratch (static device globals; no allocation) ----
__device__ __align__(128) float g_bufX[N_NODES * D];   // h2
__device__ __align__(128) float g_bufH1[N_NODES * D];  // h1 -> A
__device__ __align__(128) float g_bufG[N_NODES * D];   // g  -> B
__device__ float g_dinv[N_NODES];
__device__ int   g_cnt[N_NODES];
__device__ int   g_off[N_NODES + 1];
__device__ int   g_cur[N_NODES];
// AoS edge record in dst-sorted order: {src, dst, orig_eid, w(bits)}
__device__ __align__(16) int4 g_edge[N_EDGES];

// ---- packed f32x2 helpers ----
__device__ __forceinline__ ull pack2(float lo, float hi) {
    ull r;
    asm("mov.b64 %0, {%1, %2};" : "=l"(r) : "f"(lo), "f"(hi));
    return r;
}
__device__ __forceinline__ void fma2(ull& acc, ull a, ull b) {
    asm("fma.rn.f32x2 %0, %1, %2, %3;" : "=l"(acc) : "l"(a), "l"(b), "l"(acc));
}
__device__ __forceinline__ float2 unpack2(ull v) {
    float2 r;
    asm("mov.b64 {%0, %1}, %2;" : "=f"(r.x), "=f"(r.y) : "l"(v));
    return r;
}

// ---- CSR build ----
__global__ void k_count(const int* __restrict__ dst) {
    int t = blockIdx.x * blockDim.x + threadIdx.x;
    int e0 = t * 4;
    if (e0 + 4 <= N_EDGES) {
        int4 d4 = *(const int4*)&dst[e0];
        atomicAdd(&g_cnt[d4.x], 1);
        atomicAdd(&g_cnt[d4.y], 1);
        atomicAdd(&g_cnt[d4.z], 1);
        atomicAdd(&g_cnt[d4.w], 1);
    } else {
        for (int e = e0; e < N_EDGES; e++) atomicAdd(&g_cnt[dst[e]], 1);
    }
}

// thread-coarsened single-block scan: 1024 threads x ~49 elems each
__global__ void k_scan() {
    __shared__ int warp_sums[32];
    const int CH = (N_NODES + 1023) / 1024;  // 49
    int tid = threadIdx.x;
    int lane = tid & 31, wid = tid >> 5;
    int start = tid * CH;
    int end = min(start + CH, N_NODES);
    int sum = 0;
    for (int i = start; i < end; i++) sum += g_cnt[i];
    int v = sum;
#pragma unroll
    for (int o = 1; o < 32; o <<= 1) {
        int t = __shfl_up_sync(0xffffffffu, v, o);
        if (lane >= o) v += t;
    }
    if (lane == 31) warp_sums[wid] = v;
    __syncthreads();
    if (wid == 0) {
        int s = warp_sums[lane];
#pragma unroll
        for (int o = 1; o < 32; o <<= 1) {
            int t = __shfl_up_sync(0xffffffffu, s, o);
            if (lane >= o) s += t;
        }
        warp_sums[lane] = s;
    }
    __syncthreads();
    int run = v - sum + (wid > 0 ? warp_sums[wid - 1] : 0);  // exclusive prefix
    for (int i = start; i < end; i++) {
        int c = g_cnt[i];
        g_cur[i] = run;
        run += c;
        g_off[i + 1] = run;
        g_dinv[i] = rsqrtf((float)c + 1.0f);  // deg = cnt + 1 (self-loop)
    }
    if (tid == 0) g_off[0] = 0;
}

__global__ void k_fill(const int* __restrict__ src, const int* __restrict__ dst) {
    int t = blockIdx.x * blockDim.x + threadIdx.x;
    int e0 = t * 4;
    if (e0 >= N_EDGES) return;
    int4 s4 = *(const int4*)&src[e0];
    int4 d4 = *(const int4*)&dst[e0];
#pragma unroll
    for (int j = 0; j < 4; j++) {
        int s = (j == 0) ? s4.x : (j == 1) ? s4.y : (j == 2) ? s4.z : s4.w;
        int d = (j == 0) ? d4.x : (j == 1) ? d4.y : (j == 2) ? d4.z : d4.w;
        int p = atomicAdd(&g_cur[d], 1);
        float w = g_dinv[s] * g_dinv[d];
        g_edge[p] = make_int4(s, d, e0 + j, __float_as_int(w));
    }
}

// ---- fused layer-1: h1 = relu( agg(x) @ W1 + b1 ), warp per node ----
__global__ void __launch_bounds__(256) k_layer1(
    const float* __restrict__ x, const float* __restrict__ W1,
    const float* __restrict__ b1, float* __restrict__ H) {
    __shared__ float sW1[D_IN * D];
    for (int i = threadIdx.x * 4; i < D_IN * D; i += 256 * 4)
        *(float4*)&sW1[i] = *(const float4*)&W1[i];
    __syncthreads();
    int n = (blockIdx.x * blockDim.x + threadIdx.x) >> 5;
    if (n >= N_NODES) return;
    int lane = threadIdx.x & 31;
    int grp = lane >> 3;    // 0..3
    int dim = lane & 7;     // 0..7
    float di = g_dinv[n];
    float acc = (grp == 0) ? x[n * D_IN + dim] * di * di : 0.f;
    float acc2 = 0.f;
    int i0 = g_off[n], i1 = g_off[n + 1];
    int i = i0 + grp;
    // 2 gathers in flight per lane-group
    for (; i + 4 < i1; i += 8) {
        int4 ea = g_edge[i];
        int4 eb = g_edge[i + 4];
        float va = x[ea.x * D_IN + dim];
        float vb = x[eb.x * D_IN + dim];
        acc = fmaf(va, __int_as_float(ea.w), acc);
        acc2 = fmaf(vb, __int_as_float(eb.w), acc2);
    }
    if (i < i1) {
        int4 ea = g_edge[i];
        acc = fmaf(x[ea.x * D_IN + dim], __int_as_float(ea.w), acc);
    }
    acc += acc2;
    // reduce across the 4 groups
    acc += __shfl_xor_sync(0xffffffffu, acc, 8);
    acc += __shfl_xor_sync(0xffffffffu, acc, 16);
    // broadcast all 8 aggregated dims to every lane
    float xav[D_IN];
#pragma unroll
    for (int k = 0; k < D_IN; k++)
        xav[k] = __shfl_sync(0xffffffffu, acc, k);
    // project: 4 output cols per lane
    float4 o = *(const float4*)&b1[lane * 4];
#pragma unroll
    for (int k = 0; k < D_IN; k++) {
        float4 w = *(const float4*)&sW1[k * D + lane * 4];
        o.x = fmaf(xav[k], w.x, o.x);
        o.y = fmaf(xav[k], w.y, o.y);
        o.z = fmaf(xav[k], w.z, o.z);
        o.w = fmaf(xav[k], w.w, o.w);
    }
    o = make_float4(fmaxf(o.x, 0.f), fmaxf(o.y, 0.f), fmaxf(o.z, 0.f), fmaxf(o.w, 0.f));
    *(float4*)&H[n * D + lane * 4] = o;
}

// ---- 128-dim aggregation + bias + relu: warp per node, float4 lanes, 4-wide MLP ----
__global__ void k_aggregate(const float* __restrict__ Hin, const float* __restrict__ bias,
                            float* __restrict__ Hout) {
    int n = (blockIdx.x * blockDim.x + threadIdx.x) >> 5;
    int lane = threadIdx.x & 31;
    if (n >= N_NODES) return;
    float di = g_dinv[n];
    float wself = di * di;
    float4 self = *(const float4*)&Hin[n * D + lane * 4];
    float4 acc = make_float4(self.x * wself, self.y * wself, self.z * wself, self.w * wself);
    int i0 = g_off[n], i1 = g_off[n + 1];
    int i = i0;
    for (; i + 4 <= i1; i += 4) {
        int4 e0 = g_edge[i], e1 = g_edge[i + 1], e2 = g_edge[i + 2], e3 = g_edge[i + 3];
        float w0 = __int_as_float(e0.w), w1 = __int_as_float(e1.w);
        float w2 = __int_as_float(e2.w), w3 = __int_as_float(e3.w);
        float4 v0 = *(const float4*)&Hin[e0.x * D + lane * 4];
        float4 v1 = *(const float4*)&Hin[e1.x * D + lane * 4];
        float4 v2 = *(const float4*)&Hin[e2.x * D + lane * 4];
        float4 v3 = *(const float4*)&Hin[e3.x * D + lane * 4];
        acc.x = fmaf(v0.x, w0, acc.x); acc.y = fmaf(v0.y, w0, acc.y);
        acc.z = fmaf(v0.z, w0, acc.z); acc.w = fmaf(v0.w, w0, acc.w);
        acc.x = fmaf(v1.x, w1, acc.x); acc.y = fmaf(v1.y, w1, acc.y);
        acc.z = fmaf(v1.z, w1, acc.z); acc.w = fmaf(v1.w, w1, acc.w);
        acc.x = fmaf(v2.x, w2, acc.x); acc.y = fmaf(v2.y, w2, acc.y);
        acc.z = fmaf(v2.z, w2, acc.z); acc.w = fmaf(v2.w, w2, acc.w);
        acc.x = fmaf(v3.x, w3, acc.x); acc.y = fmaf(v3.y, w3, acc.y);
        acc.z = fmaf(v3.z, w3, acc.z); acc.w = fmaf(v3.w, w3, acc.w);
    }
    for (; i < i1; i++) {
        int4 e0 = g_edge[i];
        float w0 = __int_as_float(e0.w);
        float4 v0 = *(const float4*)&Hin[e0.x * D + lane * 4];
        acc.x = fmaf(v0.x, w0, acc.x); acc.y = fmaf(v0.y, w0, acc.y);
        acc.z = fmaf(v0.z, w0, acc.z); acc.w = fmaf(v0.w, w0, acc.w);
    }
    float4 bv = *(const float4*)&bias[lane * 4];
    float4 o = make_float4(fmaxf(acc.x + bv.x, 0.f), fmaxf(acc.y + bv.y, 0.f),
                           fmaxf(acc.z + bv.z, 0.f), fmaxf(acc.w + bv.w, 0.f));
    *(float4*)&Hout[n * D + lane * 4] = o;
}

// ---- persistent dense C[M,128] = H[M,128] @ W[128,128] (+opt bias) ----
// K-paired f32x2: acc.lo accumulates even k, acc.hi odd k; add halves at end.
// W pre-interleaved into smem as 64-bit (W[2k2][j], W[2k2+1][j]) pairs.
// Lane l owns cols {l, l+32, l+64, l+96} -> conflict-free LDS.64 on W pairs.
__global__ void __launch_bounds__(256, 2) k_gemm128(
    const float* __restrict__ H, const float* __restrict__ W,
    const float* __restrict__ bias, float* __restrict__ C) {
    extern __shared__ float smem[];
    ull* Ws2 = (ull*)smem;                    // 64 * 128 pairs = 64 KB
    float* Hs = (float*)(smem + 2 * 64 * D);  // 64 * 128 floats = 32 KB
    int tid = threadIdx.x;
    // interleave W once per CTA
    for (int idx = tid; idx < 64 * D; idx += 256) {
        int k2 = idx >> 7, j = idx & 127;
        Ws2[idx] = pack2(W[(2 * k2) * D + j], W[(2 * k2 + 1) * D + j]);
    }
    int warp = tid >> 5, lane = tid & 31;
    float bias_v[4];
#pragma unroll
    for (int m = 0; m < 4; m++)
        bias_v[m] = bias ? bias[lane + 32 * m] : 0.f;

    for (int t = blockIdx.x; t < GEMM_TILES; t += gridDim.x) {
        int row0 = t * 64;
        __syncthreads();  // protect Hs from previous tile's readers
        for (int i = tid * 4; i < 64 * D; i += 256 * 4) {
            int r = row0 + (i >> 7);
            float4 v = make_float4(0.f, 0.f, 0.f, 0.f);
            if (r < N_NODES) v = *(const float4*)&H[r * D + (i & 127)];
            *(float4*)&Hs[i] = v;
        }
        __syncthreads();

        ull acc[8][4];
#pragma unroll
        for (int n = 0; n < 8; n++)
#pragma unroll
            for (int m = 0; m < 4; m++) acc[n][m] = 0ull;

        const float* hrow = &Hs[warp * 8 * D];
#pragma unroll 4
        for (int k4 = 0; k4 < 32; k4++) {   // 4 k per iter
            ulonglong2 hp[8];
#pragma unroll
            for (int n = 0; n < 8; n++)
                hp[n] = *(const ulonglong2*)&hrow[n * D + k4 * 4];
            // sub-step 0: k pair (4k4, 4k4+1)
            {
                ull w2[4];
#pragma unroll
                for (int m = 0; m < 4; m++)
                    w2[m] = Ws2[(2 * k4) * D + lane + 32 * m];
#pragma unroll
                for (int n = 0; n < 8; n++)
#pragma unroll
                    for (int m = 0; m < 4; m++)
                        fma2(acc[n][m], hp[n].x, w2[m]);
            }
            // sub-step 1: k pair (4k4+2, 4k4+3)
            {
                ull w2[4];
#pragma unroll
                for (int m = 0; m < 4; m++)
                    w2[m] = Ws2[(2 * k4 + 1) * D + lane + 32 * m];
#pragma unroll
                for (int n = 0; n < 8; n++)
#pragma unroll
                    for (int m = 0; m < 4; m++)
                        fma2(acc[n][m], hp[n].y, w2[m]);
            }
        }
#pragma unroll
        for (int n = 0; n < 8; n++) {
            int r = row0 + warp * 8 + n;
            if (r < N_NODES) {
#pragma unroll
                for (int m = 0; m < 4; m++) {
                    float2 p = unpack2(acc[n][m]);
                    C[r * D + lane + 32 * m] = p.x + p.y + bias_v[m];
                }
            }
        }
    }
}

// ---- per-edge head over dst-sorted records (B rows reused via L1) ----
__global__ void k_edge_out(const float* __restrict__ A, const float* __restrict__ B,
                           const float* __restrict__ Wfin, const float* __restrict__ bfin,
                           float* __restrict__ out) {
    int gid = blockIdx.x * blockDim.x + threadIdx.x;
    int p = gid >> 5;
    int lane = gid & 31;
    if (p >= N_EDGES) return;
    int4 ed = g_edge[p];   // {src, dst, eid, w}
    float4 a = *(const float4*)&A[ed.x * D + lane * 4];
    float4 b = *(const float4*)&B[ed.y * D + lane * 4];
    float v0 = fmaxf(a.x + b.x, 0.f);
    float v1 = fmaxf(a.y + b.y, 0.f);
    float v2 = fmaxf(a.z + b.z, 0.f);
    float v3 = fmaxf(a.w + b.w, 0.f);
    float4 w01 = *(const float4*)&Wfin[lane * 8];
    float4 w23 = *(const float4*)&Wfin[lane * 8 + 4];
    float l0 = v0 * w01.x + v1 * w01.z + v2 * w23.x + v3 * w23.z;
    float l1 = v0 * w01.y + v1 * w01.w + v2 * w23.y + v3 * w23.w;
#pragma unroll
    for (int o = 16; o; o >>= 1) {
        l0 += __shfl_xor_sync(0xffffffffu, l0, o);
        l1 += __shfl_xor_sync(0xffffffffu, l1, o);
    }
    if (lane == 0) {
        l0 += bfin[0];
        l1 += bfin[1];
        float m = fmaxf(l0, l1);
        float lse = m + __logf(__expf(l0 - m) + __expf(l1 - m));
        *(float2*)&out[2 * ed.z] = make_float2(l0 - lse, l1 - lse);
    }
}

extern "C" void kernel_launch(void* const* d_in, const int* in_sizes, int n_in,
                              void* d_out, int out_size) {
    const float* x     = (const float*)d_in[0];
    const int*   ei    = (const int*)d_in[1];
    const float* W1    = (const float*)d_in[2];
    const float* b1    = (const float*)d_in[3];
    const float* W2    = (const float*)d_in[4];
    const float* b2    = (const float*)d_in[5];
    const float* Wlin1 = (const float*)d_in[6];
    const float* blin1 = (const float*)d_in[7];
    const float* Wfin  = (const float*)d_in[8];
    const float* bfin  = (const float*)d_in[9];
    const int* src = ei;
    const int* dst = ei + N_EDGES;
    float* out = (float*)d_out;

    void *pX, *pH1, *pG, *pCnt;
    cudaGetSymbolAddress(&pX, g_bufX);
    cudaGetSymbolAddress(&pH1, g_bufH1);
    cudaGetSymbolAddress(&pG, g_bufG);
    cudaGetSymbolAddress(&pCnt, g_cnt);
    float* bufX  = (float*)pX;
    float* bufH1 = (float*)pH1;
    float* bufG  = (float*)pG;

    const int gemm_smem = (64 * D * 2 + 64 * D) * 4;  // 64KB Ws2 + 32KB Hs = 96 KB
    cudaFuncSetAttribute(k_gemm128, cudaFuncAttributeMaxDynamicSharedMemorySize, gemm_smem);

    // graph structure (rebuilt every call)
    cudaMemsetAsync(pCnt, 0, N_NODES * sizeof(int));
    k_count<<<(N_EDGES / 4 + 255) / 256, 256>>>(dst);
    k_scan<<<1, 1024>>>();
    k_fill<<<(N_EDGES / 4 + 255) / 256, 256>>>(src, dst);

    // layer 1: fused aggregate(x) + projection + bias + relu
    k_layer1<<<(N_NODES * 32 + 255) / 256, 256>>>(x, W1, b1, bufH1);      // h1

    // layer 2
    k_gemm128<<<GEMM_GRID, 256, gemm_smem>>>(bufH1, W2, nullptr, bufG);   // g
    k_aggregate<<<(N_NODES * 32 + 255) / 256, 256>>>(bufG, b2, bufX);     // h2

    // per-node halves of the edge MLP (concat trick)
    k_gemm128<<<GEMM_GRID, 256, gemm_smem>>>(bufX, Wlin1, blin1, bufH1);          // A
    k_gemm128<<<GEMM_GRID, 256, gemm_smem>>>(bufX, Wlin1 + D * D, nullptr, bufG); // B

    // per-edge head over dst-sorted order
    k_edge_out<<<(N_EDGES * 32 + 255) / 256, 256>>>(bufH1, bufG, Wfin, bfin, out);
}